// round 7
// baseline (speedup 1.0000x reference)
#include <cuda_runtime.h>
#include <math.h>

#define NN 8192
#define DD 1152
#define EE 262144

typedef unsigned int uint32;

// -------- scratch (allocation-free: static device globals) --------
__device__ float g_q[(size_t)NN * DD];
__device__ float g_k[(size_t)NN * DD];
__device__ float g_v[(size_t)NN * DD];
__device__ float g_o[(size_t)NN * DD];

// -------- tf32 mma helper (HW reads regs as tf32; low bits ignored) --------
__device__ __forceinline__ void mma_tf32(float* d,
                                         uint32 a0, uint32 a1, uint32 a2, uint32 a3,
                                         uint32 b0, uint32 b1) {
    asm("mma.sync.aligned.m16n8k8.row.col.f32.tf32.tf32.f32 "
        "{%0,%1,%2,%3}, {%4,%5,%6,%7}, {%8,%9}, {%0,%1,%2,%3};"
        : "+f"(d[0]), "+f"(d[1]), "+f"(d[2]), "+f"(d[3])
        : "r"(a0), "r"(a1), "r"(a2), "r"(a3), "r"(b0), "r"(b1));
}

// -------- cp.async helpers --------
__device__ __forceinline__ void cp16(void* smem, const void* gmem) {
    uint32 s = (uint32)__cvta_generic_to_shared(smem);
    asm volatile("cp.async.cg.shared.global [%0], [%1], 16;" :: "r"(s), "l"(gmem));
}
__device__ __forceinline__ void cp_commit() { asm volatile("cp.async.commit_group;"); }
__device__ __forceinline__ void cp_wait0()  { asm volatile("cp.async.wait_group 0;"); }

// ====================== rot kernel (smem-staged coalesced output) ======================
__global__ void rot_kernel(const float* __restrict__ ev,
                           const float* __restrict__ er,
                           float* __restrict__ rot)
{
    __shared__ float Rs[256 * 9];
    int e = blockIdx.x * 256 + threadIdx.x;
    float vx = ev[3*e+0], vy = ev[3*e+1], vz = ev[3*e+2];
    float dist = sqrtf(vx*vx + vy*vy + vz*vz);
    float nx0 = vx/dist, nx1 = vy/dist, nx2 = vz/dist;

    float r0 = er[3*e+0]-0.5f, r1 = er[3*e+1]-0.5f, r2 = er[3*e+2]-0.5f;
    float rn = sqrtf(r0*r0 + r1*r1 + r2*r2);
    float a0 = r0/rn, a1 = r1/rn, a2 = r2/rn;
    float b0 = -a1, b1 = a0, b2 = a2;
    float c0 = a0, c1 = -a2, c2 = a1;

    float da = fabsf(a0*nx0 + a1*nx1 + a2*nx2);
    float db = fabsf(b0*nx0 + b1*nx1 + b2*nx2);
    float dc = fabsf(c0*nx0 + c1*nx1 + c2*nx2);

    float e0 = a0, e1 = a1, e2c_ = a2, dcur = da;
    if (dcur > db) { e0 = b0; e1 = b1; e2c_ = b2; dcur = db; }
    if (dcur > dc) { e0 = c0; e1 = c1; e2c_ = c2; }

    float z0 = nx1*e2c_ - nx2*e1;
    float z1 = nx2*e0   - nx0*e2c_;
    float z2 = nx0*e1   - nx1*e0;
    float zn = sqrtf(z0*z0 + z1*z1 + z2*z2);
    z0 /= zn; z1 /= zn; z2 /= zn;
    float y0 = nx1*z2 - nx2*z1;
    float y1 = nx2*z0 - nx0*z2;
    float y2 = nx0*z1 - nx1*z0;
    float yn = sqrtf(y0*y0 + y1*y1 + y2*y2);
    y0 /= yn; y1 /= yn; y2 /= yn;

    float* R = Rs + threadIdx.x * 9;   // stride 9: coprime with 32, conflict-free
    R[0] =  z0; R[1] =  z1; R[2] =  z2;
    R[3] = nx0; R[4] = nx1; R[5] = nx2;
    R[6] = -y0; R[7] = -y1; R[8] = -y2;
    __syncthreads();

    float* gb = rot + (size_t)blockIdx.x * 256 * 9;
    for (int j = threadIdx.x; j < 576; j += 256)
        *(float4*)&gb[j*4] = *(float4*)&Rs[j*4];
}

#define PL 132

// ====================== fused QKV linear (TF32 mma, staged output) ======================
template<int L>
__global__ void __launch_bounds__(256) qkv_tf32(const float* __restrict__ x,
                                                const float* __restrict__ Wq,
                                                const float* __restrict__ Wk,
                                                const float* __restrict__ Wv,
                                                float* __restrict__ q,
                                                float* __restrict__ k,
                                                float* __restrict__ v)
{
    constexpr int d = 2*L + 1;
    constexpr int s = (L == 0) ? 0 : (L == 1 ? 128 : 512);
    constexpr int ntiles = (NN * d) / 64;

    extern __shared__ float sm[];
    float* As = sm;             // [64][132]; reused as staging [3][64][34] after mma
    float* Bs = sm + 64*PL;     // [3][32][132]

    const int tid  = threadIdx.x;
    const int lane = tid & 31, wid = tid >> 5;
    const int gr   = lane >> 2, th = lane & 3;
    const int wr   = wid >> 1, wc = wid & 1;
    const int obase = blockIdx.y * 32;

    // --- W fill (once, cp.async raw) ---
    for (int i = tid; i < 3*32*32; i += 256) {
        int wi = i >> 10, rem = i & 1023;
        int o = rem >> 5, c4 = (rem & 31) * 4;
        const float* wp = (wi == 0) ? Wq : (wi == 1 ? Wk : Wv);
        cp16(&Bs[(wi*32 + o)*PL + c4], &wp[(obase + o)*128 + c4]);
    }
    cp_commit();

    const float scale = 0.08838834764831845f;  // 1/sqrt(128)

    for (int t = blockIdx.x; t < ntiles; t += gridDim.x) {
        const int r0 = t * 64;
        __syncthreads();   // prior iteration's staging reads done
        for (int i = tid; i < 64*128; i += 256) {
            int row = i & 63, c = i >> 6;
            int rg = r0 + row;
            int n = rg / d, m = rg - n * d;
            As[row*PL + c] = __ldg(&x[(size_t)n*DD + s + c*d + m]);
        }
        cp_wait0();        // W ready (no-op after first tile)
        __syncthreads();

        float acc[3][2][4];
        #pragma unroll
        for (int wi = 0; wi < 3; wi++)
            #pragma unroll
            for (int nt = 0; nt < 2; nt++)
                #pragma unroll
                for (int j = 0; j < 4; j++) acc[wi][nt][j] = 0.f;

        #pragma unroll 4
        for (int ks = 0; ks < 16; ks++) {
            int k0 = ks * 8;
            const float* Ar = As + k0 + th;
            uint32 a0 = __float_as_uint(Ar[(wr*16 + gr    ) * PL    ]);
            uint32 a1 = __float_as_uint(Ar[(wr*16 + gr + 8) * PL    ]);
            uint32 a2 = __float_as_uint(Ar[(wr*16 + gr    ) * PL + 4]);
            uint32 a3 = __float_as_uint(Ar[(wr*16 + gr + 8) * PL + 4]);
            #pragma unroll
            for (int wi = 0; wi < 3; wi++)
                #pragma unroll
                for (int nt = 0; nt < 2; nt++) {
                    const float* Br = Bs + (wi*32 + wc*16 + nt*8 + gr)*PL + k0 + th;
                    uint32 b0 = __float_as_uint(Br[0]);
                    uint32 b1 = __float_as_uint(Br[4]);
                    mma_tf32(acc[wi][nt], a0, a1, a2, a3, b0, b1);
                }
        }

        __syncthreads();   // all mma reads of As done -> safe to reuse as staging

        // --- stage to smem: Ss[wi][row][o_local], pitch 34 (even -> float2 OK) ---
        float* Ss = As;
        #pragma unroll
        for (int wi = 0; wi < 3; wi++)
            #pragma unroll
            for (int r = 0; r < 2; r++) {
                int row = wr*16 + gr + 8*r;
                #pragma unroll
                for (int nt = 0; nt < 2; nt++) {
                    int o = wc*16 + nt*8 + 2*th;
                    *(float2*)&Ss[(wi*64 + row)*34 + o] =
                        make_float2(acc[wi][nt][2*r]*scale, acc[wi][nt][2*r+1]*scale);
                }
            }
        __syncthreads();

        // --- coalesced write: per node, addresses (obase+o)*d+m are contiguous ---
        const int n_first = r0 / d, n_last = (r0 + 63) / d;
        const int F = (n_last - n_first + 1) * 32 * d;
        #pragma unroll
        for (int wi = 0; wi < 3; wi++) {
            float* yp = (wi == 0) ? q : (wi == 1 ? k : v);
            for (int f = tid; f < F; f += 256) {
                int n = n_first + f / (32*d);
                int w = f % (32*d);             // = o_local*d + m
                int rg = n*d + (w % d);
                if (rg >= r0 && rg < r0 + 64)
                    yp[(size_t)n*DD + s + obase*d + w] =
                        Ss[(wi*64 + rg - r0)*34 + w / d];
            }
        }
    }
}

// ====================== single linear (W_o path, staged output) ======================
template<int L>
__global__ void __launch_bounds__(256) linear_tf32(const float* __restrict__ x,
                                                   const float* __restrict__ W,
                                                   float* __restrict__ y)
{
    constexpr int d = 2*L + 1;
    constexpr int s = (L == 0) ? 0 : (L == 1 ? 128 : 512);

    extern __shared__ float sm[];
    float* As = sm;             // [64][132]; reused as staging [64][130]
    float* Bs = sm + 64*PL;     // [128][132]

    const int tid  = threadIdx.x;
    const int wid  = tid >> 5, lane = tid & 31;
    const int gr   = lane >> 2, th = lane & 3;
    const int wr   = wid >> 1, wc = wid & 1;
    const int warpRow = wr * 16;
    const int colBase = wc * 64;
    const int r0   = blockIdx.x * 64;

    const float* Wl = W + L * 16384;
    for (int i = tid; i < 4096; i += 256) {
        int o = i >> 5, c4 = (i & 31) * 4;
        cp16(&Bs[o*PL + c4], &Wl[o*128 + c4]);
    }
    cp_commit();

    for (int i = tid; i < 64*128; i += 256) {
        int row = i & 63, c = i >> 6;
        int rg = r0 + row;
        int n = rg / d, m = rg - n * d;
        As[row*PL + c] = __ldg(&x[(size_t)n*DD + s + c*d + m]);
    }
    cp_wait0();
    __syncthreads();

    float acc[8][4];
    #pragma unroll
    for (int nt = 0; nt < 8; nt++)
        #pragma unroll
        for (int j = 0; j < 4; j++) acc[nt][j] = 0.f;

    #pragma unroll 4
    for (int ks = 0; ks < 16; ks++) {
        int k0 = ks * 8;
        const float* Ar = As + k0 + th;
        uint32 a0 = __float_as_uint(Ar[(warpRow + gr    ) * PL    ]);
        uint32 a1 = __float_as_uint(Ar[(warpRow + gr + 8) * PL    ]);
        uint32 a2 = __float_as_uint(Ar[(warpRow + gr    ) * PL + 4]);
        uint32 a3 = __float_as_uint(Ar[(warpRow + gr + 8) * PL + 4]);
        #pragma unroll
        for (int nt = 0; nt < 8; nt++) {
            const float* Br = Bs + (colBase + nt*8 + gr) * PL + k0 + th;
            uint32 b0 = __float_as_uint(Br[0]);
            uint32 b1 = __float_as_uint(Br[4]);
            mma_tf32(acc[nt], a0, a1, a2, a3, b0, b1);
        }
    }

    __syncthreads();   // As reads done

    const float scale = 0.08838834764831845f;
    float* Ss = As;    // staging [64][130]
    #pragma unroll
    for (int r = 0; r < 2; r++) {
        int row = warpRow + gr + 8*r;
        #pragma unroll
        for (int nt = 0; nt < 8; nt++) {
            int o = colBase + nt*8 + 2*th;
            *(float2*)&Ss[row*130 + o] =
                make_float2(acc[nt][2*r]*scale, acc[nt][2*r+1]*scale);
        }
    }
    __syncthreads();

    const int n_first = r0 / d, n_last = (r0 + 63) / d;
    const int F = (n_last - n_first + 1) * 128 * d;
    for (int f = tid; f < F; f += 256) {
        int n = n_first + f / (128*d);
        int w = f % (128*d);               // = o*d + m
        int rg = n*d + (w % d);
        if (rg >= r0 && rg < r0 + 64)
            y[(size_t)n*DD + s + w] = Ss[(rg - r0)*130 + w / d];
    }
}

// ====================== flash attention (TF32, staged O output) ======================
#define PQ 148
#define PVP 152
#define PP 52

__global__ void __launch_bounds__(128) attn_kernel(const float* __restrict__ q,
                                                   const float* __restrict__ k,
                                                   const float* __restrict__ v,
                                                   float* __restrict__ o)
{
    extern __shared__ float sm[];
    float* Qs = sm;               // [64][148]; reused as O staging at the end
    float* Ks = Qs + 64*PQ;       // [32][148]
    float* Vs = Ks + 32*PQ;       // [32][152]  natural [key][dim]
    float* Ps = Vs + 32*PVP;      // [64][52]

    const int tid  = threadIdx.x;
    const int wid  = tid >> 5, lane = tid & 31;
    const int gr   = lane >> 2, th = lane & 3;
    const int b    = blockIdx.y >> 3, h = blockIdx.y & 7;
    const int q0   = blockIdx.x * 64;
    const size_t hoff  = (size_t)h * 144;
    const size_t bbase = (size_t)b * 512;
    const float qscale = 1.0f / 12.0f;

    for (int f = tid; f < 64*36; f += 128) {
        int row = f / 36, cs = (f % 36) * 4;
        cp16(&Qs[row*PQ + cs], &q[(bbase + q0 + row) * DD + hoff + cs]);
    }
    cp_commit();

    float m_i[2] = {-1e30f, -1e30f};
    float l_i[2] = {0.f, 0.f};
    float oac[18][4];
    #pragma unroll
    for (int nt = 0; nt < 18; nt++)
        #pragma unroll
        for (int j = 0; j < 4; j++) oac[nt][j] = 0.f;

    const int warpRow = 16 * wid;

    for (int kt = 0; kt < 512; kt += 32) {
        __syncthreads();
        for (int f = tid; f < 32*36; f += 128) {
            int row = f / 36, cs = (f % 36) * 4;
            size_t g = (bbase + kt + row) * (size_t)DD + hoff + cs;
            cp16(&Ks[row*PQ  + cs], &k[g]);
            cp16(&Vs[row*PVP + cs], &v[g]);
        }
        cp_commit();
        cp_wait0();
        __syncthreads();

        float s_[4][4];
        #pragma unroll
        for (int nt = 0; nt < 4; nt++)
            #pragma unroll
            for (int j = 0; j < 4; j++) s_[nt][j] = 0.f;

        #pragma unroll 3
        for (int ks = 0; ks < 18; ks++) {
            int k0 = ks * 8;
            const float* Qr = Qs + k0 + th;
            uint32 a0 = __float_as_uint(Qr[(warpRow + gr    ) * PQ    ]);
            uint32 a1 = __float_as_uint(Qr[(warpRow + gr + 8) * PQ    ]);
            uint32 a2 = __float_as_uint(Qr[(warpRow + gr    ) * PQ + 4]);
            uint32 a3 = __float_as_uint(Qr[(warpRow + gr + 8) * PQ + 4]);
            #pragma unroll
            for (int nt = 0; nt < 4; nt++) {
                const float* Kr = Ks + (nt*8 + gr) * PQ + k0 + th;
                uint32 b0 = __float_as_uint(Kr[0]);
                uint32 b1 = __float_as_uint(Kr[4]);
                mma_tf32(s_[nt], a0, a1, a2, a3, b0, b1);
            }
        }

        #pragma unroll
        for (int nt = 0; nt < 4; nt++)
            #pragma unroll
            for (int j = 0; j < 4; j++) s_[nt][j] *= qscale;

        #pragma unroll
        for (int r = 0; r < 2; r++) {
            float rm = -1e30f;
            #pragma unroll
            for (int nt = 0; nt < 4; nt++)
                rm = fmaxf(rm, fmaxf(s_[nt][2*r], s_[nt][2*r+1]));
            rm = fmaxf(rm, __shfl_xor_sync(0xffffffffu, rm, 1));
            rm = fmaxf(rm, __shfl_xor_sync(0xffffffffu, rm, 2));
            float newm = fmaxf(m_i[r], rm);
            float rs = 0.f;
            #pragma unroll
            for (int nt = 0; nt < 4; nt++) {
                float p0 = __expf(s_[nt][2*r  ] - newm);
                float p1 = __expf(s_[nt][2*r+1] - newm);
                s_[nt][2*r] = p0; s_[nt][2*r+1] = p1;
                rs += p0 + p1;
            }
            rs += __shfl_xor_sync(0xffffffffu, rs, 1);
            rs += __shfl_xor_sync(0xffffffffu, rs, 2);
            float corr = __expf(m_i[r] - newm);
            l_i[r] = l_i[r] * corr + rs;
            m_i[r] = newm;
            #pragma unroll
            for (int nt = 0; nt < 18; nt++) {
                oac[nt][2*r  ] *= corr;
                oac[nt][2*r+1] *= corr;
            }
        }

        #pragma unroll
        for (int nt = 0; nt < 4; nt++) {
            int col = nt*8 + 2*th;
            Ps[(warpRow + gr    ) * PP + col    ] = s_[nt][0];
            Ps[(warpRow + gr    ) * PP + col + 1] = s_[nt][1];
            Ps[(warpRow + gr + 8) * PP + col    ] = s_[nt][2];
            Ps[(warpRow + gr + 8) * PP + col + 1] = s_[nt][3];
        }
        __syncwarp();

        #pragma unroll
        for (int ks = 0; ks < 4; ks++) {
            int k0 = ks * 8;
            const float* Pr = Ps + k0 + th;
            uint32 a0 = __float_as_uint(Pr[(warpRow + gr    ) * PP    ]);
            uint32 a1 = __float_as_uint(Pr[(warpRow + gr + 8) * PP    ]);
            uint32 a2 = __float_as_uint(Pr[(warpRow + gr    ) * PP + 4]);
            uint32 a3 = __float_as_uint(Pr[(warpRow + gr + 8) * PP + 4]);
            const float* Vb = Vs + (k0 + th) * PVP + gr;
            #pragma unroll
            for (int nt = 0; nt < 18; nt++) {
                uint32 b0 = __float_as_uint(Vb[nt*8]);
                uint32 b1 = __float_as_uint(Vb[nt*8 + 4*PVP]);
                mma_tf32(oac[nt], a0, a1, a2, a3, b0, b1);
            }
        }
    }

    // ---- stage O into Qs (dead), then coalesced float4 writeback ----
    __syncthreads();   // all warps done reading Qs
    float* Os = Qs;    // [64][148]
    #pragma unroll
    for (int r = 0; r < 2; r++) {
        float inv = 1.0f / l_i[r];
        int row = warpRow + gr + 8*r;
        #pragma unroll
        for (int nt = 0; nt < 18; nt++) {
            int col = nt*8 + 2*th;
            *(float2*)&Os[row*PQ + col] =
                make_float2(oac[nt][2*r]*inv, oac[nt][2*r+1]*inv);
        }
    }
    __syncthreads();

    for (int f = tid; f < 64*36; f += 128) {
        int row = f / 36, cs = (f % 36) * 4;
        *(float4*)&o[(bbase + q0 + row) * (size_t)DD + hoff + cs] =
            *(float4*)&Os[row*PQ + cs];
    }
}

// ====================== epilogue ======================
__global__ void __launch_bounds__(256) epilogue_kernel(const float* __restrict__ x,
                                                       const float* __restrict__ attn,
                                                       const float* __restrict__ gamma,
                                                       const float* __restrict__ beta,
                                                       float* __restrict__ out)
{
    const int n = blockIdx.x;
    const int tid = threadIdx.x;
    const size_t base = (size_t)n * DD;

    __shared__ float red[8];
    __shared__ float mu_s, rv_s;

    float val = 0.f;
    if (tid < 128) val = x[base + tid] + attn[base + tid];
    float s1 = val, s2 = val * val;
    #pragma unroll
    for (int off = 16; off; off >>= 1) {
        s1 += __shfl_xor_sync(0xffffffffu, s1, off);
        s2 += __shfl_xor_sync(0xffffffffu, s2, off);
    }
    if (tid < 128 && (tid & 31) == 0) { red[(tid>>5)*2] = s1; red[(tid>>5)*2+1] = s2; }
    __syncthreads();
    if (tid == 0) {
        float t1 = red[0] + red[2] + red[4] + red[6];
        float t2 = red[1] + red[3] + red[5] + red[7];
        float mu = t1 * (1.f/128.f);
        float var = t2 * (1.f/128.f) - mu*mu;
        mu_s = mu;
        rv_s = rsqrtf(var + 1e-5f);
    }
    __syncthreads();
    const float mu = mu_s, rv = rv_s;

    for (int i = tid; i < DD; i += 256) {
        float vv = x[base + i] + attn[base + i];
        if (i < 128) {
            float z = (vv - mu) * rv * gamma[i] + beta[i];
            vv = z / (1.f + __expf(-z));
        }
        out[base + i] = vv;
    }
}

// ====================== launch ======================
extern "C" void kernel_launch(void* const* d_in, const int* in_sizes, int n_in,
                              void* d_out, int out_size)
{
    const float* x     = (const float*)d_in[0];
    const float* ev    = (const float*)d_in[1];
    const float* er    = (const float*)d_in[2];
    const float* Wq    = (const float*)d_in[3];
    const float* Wk    = (const float*)d_in[4];
    const float* Wv    = (const float*)d_in[5];
    const float* Wo    = (const float*)d_in[6];
    const float* gamma = (const float*)d_in[7];
    const float* beta  = (const float*)d_in[8];
    float* out  = (float*)d_out;
    float* rotp = out + (size_t)NN * DD;

    float *qp, *kp, *vp, *op;
    cudaGetSymbolAddress((void**)&qp, g_q);
    cudaGetSymbolAddress((void**)&kp, g_k);
    cudaGetSymbolAddress((void**)&vp, g_v);
    cudaGetSymbolAddress((void**)&op, g_o);

    const int SMF = (64*PL + 3*32*PL) * 4;                       // 84480
    const int SML = (64*PL + 128*PL) * 4;                        // 101376
    const int SMA = (64*PQ + 32*PQ + 32*PVP + 64*PP) * 4;        // 89600

    cudaFuncSetAttribute((const void*)qkv_tf32<0>,    cudaFuncAttributeMaxDynamicSharedMemorySize, SMF);
    cudaFuncSetAttribute((const void*)qkv_tf32<1>,    cudaFuncAttributeMaxDynamicSharedMemorySize, SMF);
    cudaFuncSetAttribute((const void*)qkv_tf32<2>,    cudaFuncAttributeMaxDynamicSharedMemorySize, SMF);
    cudaFuncSetAttribute((const void*)linear_tf32<0>, cudaFuncAttributeMaxDynamicSharedMemorySize, SML);
    cudaFuncSetAttribute((const void*)linear_tf32<1>, cudaFuncAttributeMaxDynamicSharedMemorySize, SML);
    cudaFuncSetAttribute((const void*)linear_tf32<2>, cudaFuncAttributeMaxDynamicSharedMemorySize, SML);
    cudaFuncSetAttribute((const void*)attn_kernel,    cudaFuncAttributeMaxDynamicSharedMemorySize, SMA);

    rot_kernel<<<EE/256, 256>>>(ev, er, rotp);

    qkv_tf32<0><<<dim3(32, 4), 256, SMF>>>(x, Wq,         Wk,         Wv,         qp, kp, vp);
    qkv_tf32<1><<<dim3(96, 4), 256, SMF>>>(x, Wq + 16384, Wk + 16384, Wv + 16384, qp, kp, vp);
    qkv_tf32<2><<<dim3(80, 4), 256, SMF>>>(x, Wq + 32768, Wk + 32768, Wv + 32768, qp, kp, vp);

    attn_kernel<<<dim3(8, 128), 128, SMA>>>(qp, kp, vp, op);

    linear_tf32<0><<<128, 256, SML>>>(op, Wo, kp);
    linear_tf32<1><<<384, 256, SML>>>(op, Wo, kp);
    linear_tf32<2><<<640, 256, SML>>>(op, Wo, kp);

    epilogue_kernel<<<NN, 256>>>(x, kp, gamma, beta, out);
}

// round 8
// speedup vs baseline: 1.3569x; 1.3569x over previous
#include <cuda_runtime.h>
#include <math.h>

#define NN 8192
#define DD 1152
#define EE 262144

typedef unsigned int uint32;

// -------- scratch (allocation-free: static device globals) --------
__device__ float g_q[(size_t)NN * DD];
__device__ float g_k[(size_t)NN * DD];
__device__ float g_v[(size_t)NN * DD];
__device__ float g_o[(size_t)NN * DD];

// -------- tf32 mma helper (HW reads regs as tf32; low bits ignored) --------
__device__ __forceinline__ void mma_tf32(float* d,
                                         uint32 a0, uint32 a1, uint32 a2, uint32 a3,
                                         uint32 b0, uint32 b1) {
    asm("mma.sync.aligned.m16n8k8.row.col.f32.tf32.tf32.f32 "
        "{%0,%1,%2,%3}, {%4,%5,%6,%7}, {%8,%9}, {%0,%1,%2,%3};"
        : "+f"(d[0]), "+f"(d[1]), "+f"(d[2]), "+f"(d[3])
        : "r"(a0), "r"(a1), "r"(a2), "r"(a3), "r"(b0), "r"(b1));
}

// -------- cp.async helpers --------
__device__ __forceinline__ void cp16(void* smem, const void* gmem) {
    uint32 s = (uint32)__cvta_generic_to_shared(smem);
    asm volatile("cp.async.cg.shared.global [%0], [%1], 16;" :: "r"(s), "l"(gmem));
}
__device__ __forceinline__ void cp_commit() { asm volatile("cp.async.commit_group;"); }
__device__ __forceinline__ void cp_wait0()  { asm volatile("cp.async.wait_group 0;"); }

// ====================== rot kernel ======================
__global__ void rot_kernel(const float* __restrict__ ev,
                           const float* __restrict__ er,
                           float* __restrict__ rot)
{
    int e = blockIdx.x * 256 + threadIdx.x;
    if (e >= EE) return;
    float vx = ev[3*e+0], vy = ev[3*e+1], vz = ev[3*e+2];
    float dist = sqrtf(vx*vx + vy*vy + vz*vz);
    float nx0 = vx/dist, nx1 = vy/dist, nx2 = vz/dist;

    float r0 = er[3*e+0]-0.5f, r1 = er[3*e+1]-0.5f, r2 = er[3*e+2]-0.5f;
    float rn = sqrtf(r0*r0 + r1*r1 + r2*r2);
    float a0 = r0/rn, a1 = r1/rn, a2 = r2/rn;
    float b0 = -a1, b1 = a0, b2 = a2;
    float c0 = a0, c1 = -a2, c2 = a1;

    float da = fabsf(a0*nx0 + a1*nx1 + a2*nx2);
    float db = fabsf(b0*nx0 + b1*nx1 + b2*nx2);
    float dc = fabsf(c0*nx0 + c1*nx1 + c2*nx2);

    float e0 = a0, e1 = a1, e2c_ = a2, dcur = da;
    if (dcur > db) { e0 = b0; e1 = b1; e2c_ = b2; dcur = db; }
    if (dcur > dc) { e0 = c0; e1 = c1; e2c_ = c2; }

    float z0 = nx1*e2c_ - nx2*e1;
    float z1 = nx2*e0   - nx0*e2c_;
    float z2 = nx0*e1   - nx1*e0;
    float zn = sqrtf(z0*z0 + z1*z1 + z2*z2);
    z0 /= zn; z1 /= zn; z2 /= zn;
    float y0 = nx1*z2 - nx2*z1;
    float y1 = nx2*z0 - nx0*z2;
    float y2 = nx0*z1 - nx1*z0;
    float yn = sqrtf(y0*y0 + y1*y1 + y2*y2);
    y0 /= yn; y1 /= yn; y2 /= yn;

    float* R = rot + (size_t)e * 9;
    R[0] =  z0; R[1] =  z1; R[2] =  z2;
    R[3] = nx0; R[4] = nx1; R[5] = nx2;
    R[6] = -y0; R[7] = -y1; R[8] = -y2;
}

#define PL 132

// ====================== fused QKV linear (TF32 mma, natural-layout A via cp.async) ======================
// Block covers 32 output-cols (blockIdx.y) x 3 weights, loops row-tiles of 64.
// X loaded as whole node rows (contiguous) via cp.async; A-frags read with stride d.
template<int L>
__global__ void __launch_bounds__(256) qkv_tf32(const float* __restrict__ x,
                                                const float* __restrict__ Wq,
                                                const float* __restrict__ Wk,
                                                const float* __restrict__ Wv,
                                                float* __restrict__ q,
                                                float* __restrict__ k,
                                                float* __restrict__ v)
{
    constexpr int d = 2*L + 1;
    constexpr int s = (L == 0) ? 0 : (L == 1 ? 128 : 512);
    constexpr int ntiles = (NN * d) / 64;
    constexpr int PX = 128*d + 4;       // node-row pitch (mult of 4 for cp16 alignment)
    constexpr int NMAX = 64/d + 2;      // max nodes spanned by a 64-row tile

    extern __shared__ float sm[];
    float* Xs = sm;                 // [NMAX][PX] natural node rows
    float* Bs = sm + NMAX*PX;       // [3][32][132]

    const int tid  = threadIdx.x;
    const int lane = tid & 31, wid = tid >> 5;
    const int gr   = lane >> 2, th = lane & 3;
    const int wr   = wid >> 1, wc = wid & 1;
    const int obase = blockIdx.y * 32;

    // --- W fill (once, cp.async raw) ---
    for (int i = tid; i < 3*32*32; i += 256) {
        int wi = i >> 10, rem = i & 1023;
        int o = rem >> 5, c4 = (rem & 31) * 4;
        const float* wp = (wi == 0) ? Wq : (wi == 1 ? Wk : Wv);
        cp16(&Bs[(wi*32 + o)*PL + c4], &wp[(obase + o)*128 + c4]);
    }
    cp_commit();

    const float scale = 0.08838834764831845f;  // 1/sqrt(128)

    for (int t = blockIdx.x; t < ntiles; t += gridDim.x) {
        const int r0 = t * 64;
        const int n0 = r0 / d;
        const int n1 = (r0 + 63) / d;
        const int cnt = n1 - n0 + 1;

        __syncthreads();   // prior iteration's Xs readers done
        for (int i = tid; i < cnt*32*d; i += 256) {
            int node = i / (32*d);
            int j = (i - node*32*d) * 4;
            cp16(&Xs[node*PX + j], &x[(size_t)(n0+node)*DD + s + j]);
        }
        cp_commit();
        cp_wait0();        // waits W too on first tile
        __syncthreads();

        // per-thread A base pointers (rows wr*16+gr and +8)
        const int rowA0 = r0 + wr*16 + gr;
        const int rowA1 = rowA0 + 8;
        const int nA0 = rowA0 / d, mA0 = rowA0 - nA0*d;
        const int nA1 = rowA1 / d, mA1 = rowA1 - nA1*d;
        const float* X0 = Xs + (nA0 - n0)*PX + mA0 + th*d;
        const float* X1 = Xs + (nA1 - n0)*PX + mA1 + th*d;

        float acc[3][2][4];
        #pragma unroll
        for (int wi = 0; wi < 3; wi++)
            #pragma unroll
            for (int nt = 0; nt < 2; nt++)
                #pragma unroll
                for (int j = 0; j < 4; j++) acc[wi][nt][j] = 0.f;

        #pragma unroll 4
        for (int ks = 0; ks < 16; ks++) {
            const int co = ks * 8 * d;
            uint32 a0 = __float_as_uint(X0[co      ]);
            uint32 a1 = __float_as_uint(X1[co      ]);
            uint32 a2 = __float_as_uint(X0[co + 4*d]);
            uint32 a3 = __float_as_uint(X1[co + 4*d]);
            #pragma unroll
            for (int wi = 0; wi < 3; wi++)
                #pragma unroll
                for (int nt = 0; nt < 2; nt++) {
                    const float* Br = Bs + (wi*32 + wc*16 + nt*8 + gr)*PL + ks*8 + th;
                    uint32 b0 = __float_as_uint(Br[0]);
                    uint32 b1 = __float_as_uint(Br[4]);
                    mma_tf32(acc[wi][nt], a0, a1, a2, a3, b0, b1);
                }
        }

        // --- direct strided stores (R6-proven) ---
        #pragma unroll
        for (int wi = 0; wi < 3; wi++) {
            float* yp = (wi == 0) ? q : (wi == 1 ? k : v);
            #pragma unroll
            for (int r = 0; r < 2; r++) {
                int rg = r0 + wr*16 + gr + 8*r;
                int n = rg / d, m = rg - n * d;
                float* yb = yp + (size_t)n*DD + s + m;
                #pragma unroll
                for (int nt = 0; nt < 2; nt++) {
                    int o = obase + wc*16 + nt*8 + 2*th;
                    yb[(o  )*d] = acc[wi][nt][2*r  ] * scale;
                    yb[(o+1)*d] = acc[wi][nt][2*r+1] * scale;
                }
            }
        }
    }
}

// ====================== single linear (W_o path; R6-proven) ======================
template<int L>
__global__ void __launch_bounds__(256) linear_tf32(const float* __restrict__ x,
                                                   const float* __restrict__ W,
                                                   float* __restrict__ y)
{
    constexpr int d = 2*L + 1;
    constexpr int s = (L == 0) ? 0 : (L == 1 ? 128 : 512);

    extern __shared__ float sm[];
    float* As = sm;             // [64][132]
    float* Bs = sm + 64*PL;     // [128][132]

    const int tid  = threadIdx.x;
    const int wid  = tid >> 5, lane = tid & 31;
    const int gr   = lane >> 2, th = lane & 3;
    const int wr   = wid >> 1, wc = wid & 1;
    const int warpRow = wr * 16;
    const int colBase = wc * 64;
    const int r0   = blockIdx.x * 64;

    const float* Wl = W + L * 16384;
    for (int i = tid; i < 4096; i += 256) {
        int o = i >> 5, c4 = (i & 31) * 4;
        cp16(&Bs[o*PL + c4], &Wl[o*128 + c4]);
    }
    cp_commit();

    for (int i = tid; i < 64*128; i += 256) {
        int row = i & 63, c = i >> 6;
        int rg = r0 + row;
        int n = rg / d, m = rg - n * d;
        As[row*PL + c] = __ldg(&x[(size_t)n*DD + s + c*d + m]);
    }
    cp_wait0();
    __syncthreads();

    float acc[8][4];
    #pragma unroll
    for (int nt = 0; nt < 8; nt++)
        #pragma unroll
        for (int j = 0; j < 4; j++) acc[nt][j] = 0.f;

    #pragma unroll 4
    for (int ks = 0; ks < 16; ks++) {
        int k0 = ks * 8;
        const float* Ar = As + k0 + th;
        uint32 a0 = __float_as_uint(Ar[(warpRow + gr    ) * PL    ]);
        uint32 a1 = __float_as_uint(Ar[(warpRow + gr + 8) * PL    ]);
        uint32 a2 = __float_as_uint(Ar[(warpRow + gr    ) * PL + 4]);
        uint32 a3 = __float_as_uint(Ar[(warpRow + gr + 8) * PL + 4]);
        #pragma unroll
        for (int nt = 0; nt < 8; nt++) {
            const float* Br = Bs + (colBase + nt*8 + gr) * PL + k0 + th;
            uint32 b0 = __float_as_uint(Br[0]);
            uint32 b1 = __float_as_uint(Br[4]);
            mma_tf32(acc[nt], a0, a1, a2, a3, b0, b1);
        }
    }

    const float scale = 0.08838834764831845f;
    #pragma unroll
    for (int r = 0; r < 2; r++) {
        int rg = r0 + warpRow + gr + 8*r;
        int n = rg / d, m = rg - n * d;
        float* yb = y + (size_t)n*DD + s + m;
        #pragma unroll
        for (int nt = 0; nt < 8; nt++) {
            int o = colBase + nt*8 + 2*th;
            yb[(o  )*d] = acc[nt][2*r  ] * scale;
            yb[(o+1)*d] = acc[nt][2*r+1] * scale;
        }
    }
}

// ====================== flash attention (TF32, cp.async fills; R6-proven) ======================
#define PQ 148
#define PVP 152
#define PP 52

__global__ void __launch_bounds__(128) attn_kernel(const float* __restrict__ q,
                                                   const float* __restrict__ k,
                                                   const float* __restrict__ v,
                                                   float* __restrict__ o)
{
    extern __shared__ float sm[];
    float* Qs = sm;               // [64][148]
    float* Ks = Qs + 64*PQ;       // [32][148]
    float* Vs = Ks + 32*PQ;       // [32][152]  natural [key][dim]
    float* Ps = Vs + 32*PVP;      // [64][52]

    const int tid  = threadIdx.x;
    const int wid  = tid >> 5, lane = tid & 31;
    const int gr   = lane >> 2, th = lane & 3;
    const int b    = blockIdx.y >> 3, h = blockIdx.y & 7;
    const int q0   = blockIdx.x * 64;
    const size_t hoff  = (size_t)h * 144;
    const size_t bbase = (size_t)b * 512;
    const float qscale = 1.0f / 12.0f;

    for (int f = tid; f < 64*36; f += 128) {
        int row = f / 36, cs = (f % 36) * 4;
        cp16(&Qs[row*PQ + cs], &q[(bbase + q0 + row) * DD + hoff + cs]);
    }
    cp_commit();

    float m_i[2] = {-1e30f, -1e30f};
    float l_i[2] = {0.f, 0.f};
    float oac[18][4];
    #pragma unroll
    for (int nt = 0; nt < 18; nt++)
        #pragma unroll
        for (int j = 0; j < 4; j++) oac[nt][j] = 0.f;

    const int warpRow = 16 * wid;

    for (int kt = 0; kt < 512; kt += 32) {
        __syncthreads();
        for (int f = tid; f < 32*36; f += 128) {
            int row = f / 36, cs = (f % 36) * 4;
            size_t g = (bbase + kt + row) * (size_t)DD + hoff + cs;
            cp16(&Ks[row*PQ  + cs], &k[g]);
            cp16(&Vs[row*PVP + cs], &v[g]);
        }
        cp_commit();
        cp_wait0();
        __syncthreads();

        float s_[4][4];
        #pragma unroll
        for (int nt = 0; nt < 4; nt++)
            #pragma unroll
            for (int j = 0; j < 4; j++) s_[nt][j] = 0.f;

        #pragma unroll 3
        for (int ks = 0; ks < 18; ks++) {
            int k0 = ks * 8;
            const float* Qr = Qs + k0 + th;
            uint32 a0 = __float_as_uint(Qr[(warpRow + gr    ) * PQ    ]);
            uint32 a1 = __float_as_uint(Qr[(warpRow + gr + 8) * PQ    ]);
            uint32 a2 = __float_as_uint(Qr[(warpRow + gr    ) * PQ + 4]);
            uint32 a3 = __float_as_uint(Qr[(warpRow + gr + 8) * PQ + 4]);
            #pragma unroll
            for (int nt = 0; nt < 4; nt++) {
                const float* Kr = Ks + (nt*8 + gr) * PQ + k0 + th;
                uint32 b0 = __float_as_uint(Kr[0]);
                uint32 b1 = __float_as_uint(Kr[4]);
                mma_tf32(s_[nt], a0, a1, a2, a3, b0, b1);
            }
        }

        #pragma unroll
        for (int nt = 0; nt < 4; nt++)
            #pragma unroll
            for (int j = 0; j < 4; j++) s_[nt][j] *= qscale;

        #pragma unroll
        for (int r = 0; r < 2; r++) {
            float rm = -1e30f;
            #pragma unroll
            for (int nt = 0; nt < 4; nt++)
                rm = fmaxf(rm, fmaxf(s_[nt][2*r], s_[nt][2*r+1]));
            rm = fmaxf(rm, __shfl_xor_sync(0xffffffffu, rm, 1));
            rm = fmaxf(rm, __shfl_xor_sync(0xffffffffu, rm, 2));
            float newm = fmaxf(m_i[r], rm);
            float rs = 0.f;
            #pragma unroll
            for (int nt = 0; nt < 4; nt++) {
                float p0 = __expf(s_[nt][2*r  ] - newm);
                float p1 = __expf(s_[nt][2*r+1] - newm);
                s_[nt][2*r] = p0; s_[nt][2*r+1] = p1;
                rs += p0 + p1;
            }
            rs += __shfl_xor_sync(0xffffffffu, rs, 1);
            rs += __shfl_xor_sync(0xffffffffu, rs, 2);
            float corr = __expf(m_i[r] - newm);
            l_i[r] = l_i[r] * corr + rs;
            m_i[r] = newm;
            #pragma unroll
            for (int nt = 0; nt < 18; nt++) {
                oac[nt][2*r  ] *= corr;
                oac[nt][2*r+1] *= corr;
            }
        }

        #pragma unroll
        for (int nt = 0; nt < 4; nt++) {
            int col = nt*8 + 2*th;
            Ps[(warpRow + gr    ) * PP + col    ] = s_[nt][0];
            Ps[(warpRow + gr    ) * PP + col + 1] = s_[nt][1];
            Ps[(warpRow + gr + 8) * PP + col    ] = s_[nt][2];
            Ps[(warpRow + gr + 8) * PP + col + 1] = s_[nt][3];
        }
        __syncwarp();

        #pragma unroll
        for (int ks = 0; ks < 4; ks++) {
            int k0 = ks * 8;
            const float* Pr = Ps + k0 + th;
            uint32 a0 = __float_as_uint(Pr[(warpRow + gr    ) * PP    ]);
            uint32 a1 = __float_as_uint(Pr[(warpRow + gr + 8) * PP    ]);
            uint32 a2 = __float_as_uint(Pr[(warpRow + gr    ) * PP + 4]);
            uint32 a3 = __float_as_uint(Pr[(warpRow + gr + 8) * PP + 4]);
            const float* Vb = Vs + (k0 + th) * PVP + gr;
            #pragma unroll
            for (int nt = 0; nt < 18; nt++) {
                uint32 b0 = __float_as_uint(Vb[nt*8]);
                uint32 b1 = __float_as_uint(Vb[nt*8 + 4*PVP]);
                mma_tf32(oac[nt], a0, a1, a2, a3, b0, b1);
            }
        }
    }

    #pragma unroll
    for (int r = 0; r < 2; r++) {
        float inv = 1.0f / l_i[r];
        int row = q0 + warpRow + gr + 8*r;
        float* ob = o + (bbase + row) * (size_t)DD + hoff;
        #pragma unroll
        for (int nt = 0; nt < 18; nt++) {
            int col = nt*8 + 2*th;
            ob[col    ] = oac[nt][2*r  ] * inv;
            ob[col + 1] = oac[nt][2*r+1] * inv;
        }
    }
}

// ====================== epilogue ======================
__global__ void __launch_bounds__(256) epilogue_kernel(const float* __restrict__ x,
                                                       const float* __restrict__ attn,
                                                       const float* __restrict__ gamma,
                                                       const float* __restrict__ beta,
                                                       float* __restrict__ out)
{
    const int n = blockIdx.x;
    const int tid = threadIdx.x;
    const size_t base = (size_t)n * DD;

    __shared__ float red[8];
    __shared__ float mu_s, rv_s;

    float val = 0.f;
    if (tid < 128) val = x[base + tid] + attn[base + tid];
    float s1 = val, s2 = val * val;
    #pragma unroll
    for (int off = 16; off; off >>= 1) {
        s1 += __shfl_xor_sync(0xffffffffu, s1, off);
        s2 += __shfl_xor_sync(0xffffffffu, s2, off);
    }
    if (tid < 128 && (tid & 31) == 0) { red[(tid>>5)*2] = s1; red[(tid>>5)*2+1] = s2; }
    __syncthreads();
    if (tid == 0) {
        float t1 = red[0] + red[2] + red[4] + red[6];
        float t2 = red[1] + red[3] + red[5] + red[7];
        float mu = t1 * (1.f/128.f);
        float var = t2 * (1.f/128.f) - mu*mu;
        mu_s = mu;
        rv_s = rsqrtf(var + 1e-5f);
    }
    __syncthreads();
    const float mu = mu_s, rv = rv_s;

    for (int i = tid; i < DD; i += 256) {
        float vv = x[base + i] + attn[base + i];
        if (i < 128) {
            float z = (vv - mu) * rv * gamma[i] + beta[i];
            vv = z / (1.f + __expf(-z));
        }
        out[base + i] = vv;
    }
}

// ====================== launch ======================
extern "C" void kernel_launch(void* const* d_in, const int* in_sizes, int n_in,
                              void* d_out, int out_size)
{
    const float* x     = (const float*)d_in[0];
    const float* ev    = (const float*)d_in[1];
    const float* er    = (const float*)d_in[2];
    const float* Wq    = (const float*)d_in[3];
    const float* Wk    = (const float*)d_in[4];
    const float* Wv    = (const float*)d_in[5];
    const float* Wo    = (const float*)d_in[6];
    const float* gamma = (const float*)d_in[7];
    const float* beta  = (const float*)d_in[8];
    float* out  = (float*)d_out;
    float* rotp = out + (size_t)NN * DD;

    float *qp, *kp, *vp, *op;
    cudaGetSymbolAddress((void**)&qp, g_q);
    cudaGetSymbolAddress((void**)&kp, g_k);
    cudaGetSymbolAddress((void**)&vp, g_v);
    cudaGetSymbolAddress((void**)&op, g_o);

    // per-L qkv smem: NMAX*PX + 96*PL floats
    const int SMF0 = (66*132 + 96*PL) * 4;   // 85536
    const int SMF1 = (23*388 + 96*PL) * 4;   // 86384
    const int SMF2 = (14*644 + 96*PL) * 4;   // 86752
    const int SML  = (64*PL + 128*PL) * 4;   // 101376
    const int SMA  = (64*PQ + 32*PQ + 32*PVP + 64*PP) * 4;  // 89600

    cudaFuncSetAttribute((const void*)qkv_tf32<0>,    cudaFuncAttributeMaxDynamicSharedMemorySize, SMF0);
    cudaFuncSetAttribute((const void*)qkv_tf32<1>,    cudaFuncAttributeMaxDynamicSharedMemorySize, SMF1);
    cudaFuncSetAttribute((const void*)qkv_tf32<2>,    cudaFuncAttributeMaxDynamicSharedMemorySize, SMF2);
    cudaFuncSetAttribute((const void*)linear_tf32<0>, cudaFuncAttributeMaxDynamicSharedMemorySize, SML);
    cudaFuncSetAttribute((const void*)linear_tf32<1>, cudaFuncAttributeMaxDynamicSharedMemorySize, SML);
    cudaFuncSetAttribute((const void*)linear_tf32<2>, cudaFuncAttributeMaxDynamicSharedMemorySize, SML);
    cudaFuncSetAttribute((const void*)attn_kernel,    cudaFuncAttributeMaxDynamicSharedMemorySize, SMA);

    rot_kernel<<<EE/256, 256>>>(ev, er, rotp);

    qkv_tf32<0><<<dim3(32, 4), 256, SMF0>>>(x, Wq,         Wk,         Wv,         qp, kp, vp);
    qkv_tf32<1><<<dim3(96, 4), 256, SMF1>>>(x, Wq + 16384, Wk + 16384, Wv + 16384, qp, kp, vp);
    qkv_tf32<2><<<dim3(80, 4), 256, SMF2>>>(x, Wq + 32768, Wk + 32768, Wv + 32768, qp, kp, vp);

    attn_kernel<<<dim3(8, 128), 128, SMA>>>(qp, kp, vp, op);

    linear_tf32<0><<<128, 256, SML>>>(op, Wo, kp);
    linear_tf32<1><<<384, 256, SML>>>(op, Wo, kp);
    linear_tf32<2><<<640, 256, SML>>>(op, Wo, kp);

    epilogue_kernel<<<NN, 256>>>(x, kp, gamma, beta, out);
}

// round 9
// speedup vs baseline: 1.3955x; 1.0284x over previous
#include <cuda_runtime.h>
#include <math.h>

#define NN 8192
#define DD 1152
#define EE 262144

typedef unsigned int uint32;

// -------- scratch (allocation-free: static device globals) --------
__device__ float g_q[(size_t)NN * DD];
__device__ float g_k[(size_t)NN * DD];
__device__ float g_v[(size_t)NN * DD];
__device__ float g_o[(size_t)NN * DD];

// -------- tf32 mma helper (HW reads regs as tf32; low bits ignored) --------
__device__ __forceinline__ void mma_tf32(float* d,
                                         uint32 a0, uint32 a1, uint32 a2, uint32 a3,
                                         uint32 b0, uint32 b1) {
    asm("mma.sync.aligned.m16n8k8.row.col.f32.tf32.tf32.f32 "
        "{%0,%1,%2,%3}, {%4,%5,%6,%7}, {%8,%9}, {%0,%1,%2,%3};"
        : "+f"(d[0]), "+f"(d[1]), "+f"(d[2]), "+f"(d[3])
        : "r"(a0), "r"(a1), "r"(a2), "r"(a3), "r"(b0), "r"(b1));
}

// -------- cp.async helpers --------
__device__ __forceinline__ void cp16(void* smem, const void* gmem) {
    uint32 s = (uint32)__cvta_generic_to_shared(smem);
    asm volatile("cp.async.cg.shared.global [%0], [%1], 16;" :: "r"(s), "l"(gmem));
}
__device__ __forceinline__ void cp_commit() { asm volatile("cp.async.commit_group;"); }
__device__ __forceinline__ void cp_wait0()  { asm volatile("cp.async.wait_group 0;"); }

// ====================== rot kernel ======================
__global__ void rot_kernel(const float* __restrict__ ev,
                           const float* __restrict__ er,
                           float* __restrict__ rot)
{
    int e = blockIdx.x * 256 + threadIdx.x;
    if (e >= EE) return;
    float vx = ev[3*e+0], vy = ev[3*e+1], vz = ev[3*e+2];
    float dist = sqrtf(vx*vx + vy*vy + vz*vz);
    float nx0 = vx/dist, nx1 = vy/dist, nx2 = vz/dist;

    float r0 = er[3*e+0]-0.5f, r1 = er[3*e+1]-0.5f, r2 = er[3*e+2]-0.5f;
    float rn = sqrtf(r0*r0 + r1*r1 + r2*r2);
    float a0 = r0/rn, a1 = r1/rn, a2 = r2/rn;
    float b0 = -a1, b1 = a0, b2 = a2;
    float c0 = a0, c1 = -a2, c2 = a1;

    float da = fabsf(a0*nx0 + a1*nx1 + a2*nx2);
    float db = fabsf(b0*nx0 + b1*nx1 + b2*nx2);
    float dc = fabsf(c0*nx0 + c1*nx1 + c2*nx2);

    float e0 = a0, e1 = a1, e2c_ = a2, dcur = da;
    if (dcur > db) { e0 = b0; e1 = b1; e2c_ = b2; dcur = db; }
    if (dcur > dc) { e0 = c0; e1 = c1; e2c_ = c2; }

    float z0 = nx1*e2c_ - nx2*e1;
    float z1 = nx2*e0   - nx0*e2c_;
    float z2 = nx0*e1   - nx1*e0;
    float zn = sqrtf(z0*z0 + z1*z1 + z2*z2);
    z0 /= zn; z1 /= zn; z2 /= zn;
    float y0 = nx1*z2 - nx2*z1;
    float y1 = nx2*z0 - nx0*z2;
    float y2 = nx0*z1 - nx1*z0;
    float yn = sqrtf(y0*y0 + y1*y1 + y2*y2);
    y0 /= yn; y1 /= yn; y2 /= yn;

    float* R = rot + (size_t)e * 9;
    R[0] =  z0; R[1] =  z1; R[2] =  z2;
    R[3] = nx0; R[4] = nx1; R[5] = nx2;
    R[6] = -y0; R[7] = -y1; R[8] = -y2;
}

#define PL 132

// ====================== fused QKV linear (R8-proven) ======================
template<int L>
__global__ void __launch_bounds__(256) qkv_tf32(const float* __restrict__ x,
                                                const float* __restrict__ Wq,
                                                const float* __restrict__ Wk,
                                                const float* __restrict__ Wv,
                                                float* __restrict__ q,
                                                float* __restrict__ k,
                                                float* __restrict__ v)
{
    constexpr int d = 2*L + 1;
    constexpr int s = (L == 0) ? 0 : (L == 1 ? 128 : 512);
    constexpr int ntiles = (NN * d) / 64;
    constexpr int PX = 128*d + 4;
    constexpr int NMAX = 64/d + 2;

    extern __shared__ float sm[];
    float* Xs = sm;                 // [NMAX][PX] natural node rows
    float* Bs = sm + NMAX*PX;       // [3][32][132]

    const int tid  = threadIdx.x;
    const int lane = tid & 31, wid = tid >> 5;
    const int gr   = lane >> 2, th = lane & 3;
    const int wr   = wid >> 1, wc = wid & 1;
    const int obase = blockIdx.y * 32;

    for (int i = tid; i < 3*32*32; i += 256) {
        int wi = i >> 10, rem = i & 1023;
        int o = rem >> 5, c4 = (rem & 31) * 4;
        const float* wp = (wi == 0) ? Wq : (wi == 1 ? Wk : Wv);
        cp16(&Bs[(wi*32 + o)*PL + c4], &wp[(obase + o)*128 + c4]);
    }
    cp_commit();

    const float scale = 0.08838834764831845f;  // 1/sqrt(128)

    for (int t = blockIdx.x; t < ntiles; t += gridDim.x) {
        const int r0 = t * 64;
        const int n0 = r0 / d;
        const int n1 = (r0 + 63) / d;
        const int cnt = n1 - n0 + 1;

        __syncthreads();
        for (int i = tid; i < cnt*32*d; i += 256) {
            int node = i / (32*d);
            int j = (i - node*32*d) * 4;
            cp16(&Xs[node*PX + j], &x[(size_t)(n0+node)*DD + s + j]);
        }
        cp_commit();
        cp_wait0();
        __syncthreads();

        const int rowA0 = r0 + wr*16 + gr;
        const int rowA1 = rowA0 + 8;
        const int nA0 = rowA0 / d, mA0 = rowA0 - nA0*d;
        const int nA1 = rowA1 / d, mA1 = rowA1 - nA1*d;
        const float* X0 = Xs + (nA0 - n0)*PX + mA0 + th*d;
        const float* X1 = Xs + (nA1 - n0)*PX + mA1 + th*d;

        float acc[3][2][4];
        #pragma unroll
        for (int wi = 0; wi < 3; wi++)
            #pragma unroll
            for (int nt = 0; nt < 2; nt++)
                #pragma unroll
                for (int j = 0; j < 4; j++) acc[wi][nt][j] = 0.f;

        #pragma unroll 4
        for (int ks = 0; ks < 16; ks++) {
            const int co = ks * 8 * d;
            uint32 a0 = __float_as_uint(X0[co      ]);
            uint32 a1 = __float_as_uint(X1[co      ]);
            uint32 a2 = __float_as_uint(X0[co + 4*d]);
            uint32 a3 = __float_as_uint(X1[co + 4*d]);
            #pragma unroll
            for (int wi = 0; wi < 3; wi++)
                #pragma unroll
                for (int nt = 0; nt < 2; nt++) {
                    const float* Br = Bs + (wi*32 + wc*16 + nt*8 + gr)*PL + ks*8 + th;
                    uint32 b0 = __float_as_uint(Br[0]);
                    uint32 b1 = __float_as_uint(Br[4]);
                    mma_tf32(acc[wi][nt], a0, a1, a2, a3, b0, b1);
                }
        }

        #pragma unroll
        for (int wi = 0; wi < 3; wi++) {
            float* yp = (wi == 0) ? q : (wi == 1 ? k : v);
            #pragma unroll
            for (int r = 0; r < 2; r++) {
                int rg = r0 + wr*16 + gr + 8*r;
                int n = rg / d, m = rg - n * d;
                float* yb = yp + (size_t)n*DD + s + m;
                #pragma unroll
                for (int nt = 0; nt < 2; nt++) {
                    int o = obase + wc*16 + nt*8 + 2*th;
                    yb[(o  )*d] = acc[wi][nt][2*r  ] * scale;
                    yb[(o+1)*d] = acc[wi][nt][2*r+1] * scale;
                }
            }
        }
    }
}

// ====================== W_o linear (W-resident, natural-layout A, tile loop) ======================
// Block covers all 128 output cols; 8 warps = 4 row x 2 col; warp = 16 rows x 64 cols.
template<int L>
__global__ void __launch_bounds__(256) wo_tf32(const float* __restrict__ x,
                                               const float* __restrict__ W,
                                               float* __restrict__ y)
{
    constexpr int d = 2*L + 1;
    constexpr int s = (L == 0) ? 0 : (L == 1 ? 128 : 512);
    constexpr int ntiles = (NN * d) / 64;
    constexpr int PX = 128*d + 4;
    constexpr int NMAX = 64/d + 2;

    extern __shared__ float sm[];
    float* Xs = sm;                 // [NMAX][PX]
    float* Bs = sm + NMAX*PX;       // [128][132]

    const int tid  = threadIdx.x;
    const int lane = tid & 31, wid = tid >> 5;
    const int gr   = lane >> 2, th = lane & 3;
    const int wr   = wid >> 1, wc = wid & 1;
    const int warpRow = wr * 16;
    const int colBase = wc * 64;

    const float* Wl = W + L * 16384;
    for (int i = tid; i < 4096; i += 256) {
        int o = i >> 5, c4 = (i & 31) * 4;
        cp16(&Bs[o*PL + c4], &Wl[o*128 + c4]);
    }
    cp_commit();

    const float scale = 0.08838834764831845f;

    for (int t = blockIdx.x; t < ntiles; t += gridDim.x) {
        const int r0 = t * 64;
        const int n0 = r0 / d;
        const int n1 = (r0 + 63) / d;
        const int cnt = n1 - n0 + 1;

        __syncthreads();
        for (int i = tid; i < cnt*32*d; i += 256) {
            int node = i / (32*d);
            int j = (i - node*32*d) * 4;
            cp16(&Xs[node*PX + j], &x[(size_t)(n0+node)*DD + s + j]);
        }
        cp_commit();
        cp_wait0();
        __syncthreads();

        const int rowA0 = r0 + warpRow + gr;
        const int rowA1 = rowA0 + 8;
        const int nA0 = rowA0 / d, mA0 = rowA0 - nA0*d;
        const int nA1 = rowA1 / d, mA1 = rowA1 - nA1*d;
        const float* X0 = Xs + (nA0 - n0)*PX + mA0 + th*d;
        const float* X1 = Xs + (nA1 - n0)*PX + mA1 + th*d;

        float acc[8][4];
        #pragma unroll
        for (int nt = 0; nt < 8; nt++)
            #pragma unroll
            for (int j = 0; j < 4; j++) acc[nt][j] = 0.f;

        #pragma unroll 4
        for (int ks = 0; ks < 16; ks++) {
            const int co = ks * 8 * d;
            uint32 a0 = __float_as_uint(X0[co      ]);
            uint32 a1 = __float_as_uint(X1[co      ]);
            uint32 a2 = __float_as_uint(X0[co + 4*d]);
            uint32 a3 = __float_as_uint(X1[co + 4*d]);
            #pragma unroll
            for (int nt = 0; nt < 8; nt++) {
                const float* Br = Bs + (colBase + nt*8 + gr) * PL + ks*8 + th;
                uint32 b0 = __float_as_uint(Br[0]);
                uint32 b1 = __float_as_uint(Br[4]);
                mma_tf32(acc[nt], a0, a1, a2, a3, b0, b1);
            }
        }

        #pragma unroll
        for (int r = 0; r < 2; r++) {
            int rg = r0 + warpRow + gr + 8*r;
            int n = rg / d, m = rg - n * d;
            float* yb = y + (size_t)n*DD + s + m;
            #pragma unroll
            for (int nt = 0; nt < 8; nt++) {
                int o = colBase + nt*8 + 2*th;
                yb[(o  )*d] = acc[nt][2*r  ] * scale;
                yb[(o+1)*d] = acc[nt][2*r+1] * scale;
            }
        }
    }
}

// ====================== flash attention (TF32, cp.async fills; R6/R8-proven) ======================
#define PQ 148
#define PVP 152
#define PP 52

__global__ void __launch_bounds__(128) attn_kernel(const float* __restrict__ q,
                                                   const float* __restrict__ k,
                                                   const float* __restrict__ v,
                                                   float* __restrict__ o)
{
    extern __shared__ float sm[];
    float* Qs = sm;               // [64][148]
    float* Ks = Qs + 64*PQ;       // [32][148]
    float* Vs = Ks + 32*PQ;       // [32][152]
    float* Ps = Vs + 32*PVP;      // [64][52]

    const int tid  = threadIdx.x;
    const int wid  = tid >> 5, lane = tid & 31;
    const int gr   = lane >> 2, th = lane & 3;
    const int b    = blockIdx.y >> 3, h = blockIdx.y & 7;
    const int q0   = blockIdx.x * 64;
    const size_t hoff  = (size_t)h * 144;
    const size_t bbase = (size_t)b * 512;
    const float qscale = 1.0f / 12.0f;

    for (int f = tid; f < 64*36; f += 128) {
        int row = f / 36, cs = (f % 36) * 4;
        cp16(&Qs[row*PQ + cs], &q[(bbase + q0 + row) * DD + hoff + cs]);
    }
    cp_commit();

    float m_i[2] = {-1e30f, -1e30f};
    float l_i[2] = {0.f, 0.f};
    float oac[18][4];
    #pragma unroll
    for (int nt = 0; nt < 18; nt++)
        #pragma unroll
        for (int j = 0; j < 4; j++) oac[nt][j] = 0.f;

    const int warpRow = 16 * wid;

    for (int kt = 0; kt < 512; kt += 32) {
        __syncthreads();
        for (int f = tid; f < 32*36; f += 128) {
            int row = f / 36, cs = (f % 36) * 4;
            size_t g = (bbase + kt + row) * (size_t)DD + hoff + cs;
            cp16(&Ks[row*PQ  + cs], &k[g]);
            cp16(&Vs[row*PVP + cs], &v[g]);
        }
        cp_commit();
        cp_wait0();
        __syncthreads();

        float s_[4][4];
        #pragma unroll
        for (int nt = 0; nt < 4; nt++)
            #pragma unroll
            for (int j = 0; j < 4; j++) s_[nt][j] = 0.f;

        #pragma unroll 3
        for (int ks = 0; ks < 18; ks++) {
            int k0 = ks * 8;
            const float* Qr = Qs + k0 + th;
            uint32 a0 = __float_as_uint(Qr[(warpRow + gr    ) * PQ    ]);
            uint32 a1 = __float_as_uint(Qr[(warpRow + gr + 8) * PQ    ]);
            uint32 a2 = __float_as_uint(Qr[(warpRow + gr    ) * PQ + 4]);
            uint32 a3 = __float_as_uint(Qr[(warpRow + gr + 8) * PQ + 4]);
            #pragma unroll
            for (int nt = 0; nt < 4; nt++) {
                const float* Kr = Ks + (nt*8 + gr) * PQ + k0 + th;
                uint32 b0 = __float_as_uint(Kr[0]);
                uint32 b1 = __float_as_uint(Kr[4]);
                mma_tf32(s_[nt], a0, a1, a2, a3, b0, b1);
            }
        }

        #pragma unroll
        for (int nt = 0; nt < 4; nt++)
            #pragma unroll
            for (int j = 0; j < 4; j++) s_[nt][j] *= qscale;

        #pragma unroll
        for (int r = 0; r < 2; r++) {
            float rm = -1e30f;
            #pragma unroll
            for (int nt = 0; nt < 4; nt++)
                rm = fmaxf(rm, fmaxf(s_[nt][2*r], s_[nt][2*r+1]));
            rm = fmaxf(rm, __shfl_xor_sync(0xffffffffu, rm, 1));
            rm = fmaxf(rm, __shfl_xor_sync(0xffffffffu, rm, 2));
            float newm = fmaxf(m_i[r], rm);
            float rs = 0.f;
            #pragma unroll
            for (int nt = 0; nt < 4; nt++) {
                float p0 = __expf(s_[nt][2*r  ] - newm);
                float p1 = __expf(s_[nt][2*r+1] - newm);
                s_[nt][2*r] = p0; s_[nt][2*r+1] = p1;
                rs += p0 + p1;
            }
            rs += __shfl_xor_sync(0xffffffffu, rs, 1);
            rs += __shfl_xor_sync(0xffffffffu, rs, 2);
            float corr = __expf(m_i[r] - newm);
            l_i[r] = l_i[r] * corr + rs;
            m_i[r] = newm;
            #pragma unroll
            for (int nt = 0; nt < 18; nt++) {
                oac[nt][2*r  ] *= corr;
                oac[nt][2*r+1] *= corr;
            }
        }

        #pragma unroll
        for (int nt = 0; nt < 4; nt++) {
            int col = nt*8 + 2*th;
            Ps[(warpRow + gr    ) * PP + col    ] = s_[nt][0];
            Ps[(warpRow + gr    ) * PP + col + 1] = s_[nt][1];
            Ps[(warpRow + gr + 8) * PP + col    ] = s_[nt][2];
            Ps[(warpRow + gr + 8) * PP + col + 1] = s_[nt][3];
        }
        __syncwarp();

        #pragma unroll
        for (int ks = 0; ks < 4; ks++) {
            int k0 = ks * 8;
            const float* Pr = Ps + k0 + th;
            uint32 a0 = __float_as_uint(Pr[(warpRow + gr    ) * PP    ]);
            uint32 a1 = __float_as_uint(Pr[(warpRow + gr + 8) * PP    ]);
            uint32 a2 = __float_as_uint(Pr[(warpRow + gr    ) * PP + 4]);
            uint32 a3 = __float_as_uint(Pr[(warpRow + gr + 8) * PP + 4]);
            const float* Vb = Vs + (k0 + th) * PVP + gr;
            #pragma unroll
            for (int nt = 0; nt < 18; nt++) {
                uint32 b0 = __float_as_uint(Vb[nt*8]);
                uint32 b1 = __float_as_uint(Vb[nt*8 + 4*PVP]);
                mma_tf32(oac[nt], a0, a1, a2, a3, b0, b1);
            }
        }
    }

    #pragma unroll
    for (int r = 0; r < 2; r++) {
        float inv = 1.0f / l_i[r];
        int row = q0 + warpRow + gr + 8*r;
        float* ob = o + (bbase + row) * (size_t)DD + hoff;
        #pragma unroll
        for (int nt = 0; nt < 18; nt++) {
            int col = nt*8 + 2*th;
            ob[col    ] = oac[nt][2*r  ] * inv;
            ob[col + 1] = oac[nt][2*r+1] * inv;
        }
    }
}

// ====================== epilogue ======================
__global__ void __launch_bounds__(256) epilogue_kernel(const float* __restrict__ x,
                                                       const float* __restrict__ attn,
                                                       const float* __restrict__ gamma,
                                                       const float* __restrict__ beta,
                                                       float* __restrict__ out)
{
    const int n = blockIdx.x;
    const int tid = threadIdx.x;
    const size_t base = (size_t)n * DD;

    __shared__ float red[8];
    __shared__ float mu_s, rv_s;

    float val = 0.f;
    if (tid < 128) val = x[base + tid] + attn[base + tid];
    float s1 = val, s2 = val * val;
    #pragma unroll
    for (int off = 16; off; off >>= 1) {
        s1 += __shfl_xor_sync(0xffffffffu, s1, off);
        s2 += __shfl_xor_sync(0xffffffffu, s2, off);
    }
    if (tid < 128 && (tid & 31) == 0) { red[(tid>>5)*2] = s1; red[(tid>>5)*2+1] = s2; }
    __syncthreads();
    if (tid == 0) {
        float t1 = red[0] + red[2] + red[4] + red[6];
        float t2 = red[1] + red[3] + red[5] + red[7];
        float mu = t1 * (1.f/128.f);
        float var = t2 * (1.f/128.f) - mu*mu;
        mu_s = mu;
        rv_s = rsqrtf(var + 1e-5f);
    }
    __syncthreads();
    const float mu = mu_s, rv = rv_s;

    for (int i = tid; i < DD; i += 256) {
        float vv = x[base + i] + attn[base + i];
        if (i < 128) {
            float z = (vv - mu) * rv * gamma[i] + beta[i];
            vv = z / (1.f + __expf(-z));
        }
        out[base + i] = vv;
    }
}

// ====================== launch ======================
extern "C" void kernel_launch(void* const* d_in, const int* in_sizes, int n_in,
                              void* d_out, int out_size)
{
    const float* x     = (const float*)d_in[0];
    const float* ev    = (const float*)d_in[1];
    const float* er    = (const float*)d_in[2];
    const float* Wq    = (const float*)d_in[3];
    const float* Wk    = (const float*)d_in[4];
    const float* Wv    = (const float*)d_in[5];
    const float* Wo    = (const float*)d_in[6];
    const float* gamma = (const float*)d_in[7];
    const float* beta  = (const float*)d_in[8];
    float* out  = (float*)d_out;
    float* rotp = out + (size_t)NN * DD;

    float *qp, *kp, *vp, *op;
    cudaGetSymbolAddress((void**)&qp, g_q);
    cudaGetSymbolAddress((void**)&kp, g_k);
    cudaGetSymbolAddress((void**)&vp, g_v);
    cudaGetSymbolAddress((void**)&op, g_o);

    // qkv smem: NMAX*PX + 96*PL floats
    const int SMF0 = (66*132 + 96*PL) * 4;   // 85536
    const int SMF1 = (23*388 + 96*PL) * 4;   // 86384
    const int SMF2 = (14*644 + 96*PL) * 4;   // 86752
    // wo smem: NMAX*PX + 128*PL floats
    const int SMW0 = (66*132 + 128*PL) * 4;  // 102432
    const int SMW1 = (23*388 + 128*PL) * 4;  // 103280
    const int SMW2 = (14*644 + 128*PL) * 4;  // 103648
    const int SMA  = (64*PQ + 32*PQ + 32*PVP + 64*PP) * 4;  // 89600

    cudaFuncSetAttribute((const void*)qkv_tf32<0>, cudaFuncAttributeMaxDynamicSharedMemorySize, SMF0);
    cudaFuncSetAttribute((const void*)qkv_tf32<1>, cudaFuncAttributeMaxDynamicSharedMemorySize, SMF1);
    cudaFuncSetAttribute((const void*)qkv_tf32<2>, cudaFuncAttributeMaxDynamicSharedMemorySize, SMF2);
    cudaFuncSetAttribute((const void*)wo_tf32<0>,  cudaFuncAttributeMaxDynamicSharedMemorySize, SMW0);
    cudaFuncSetAttribute((const void*)wo_tf32<1>,  cudaFuncAttributeMaxDynamicSharedMemorySize, SMW1);
    cudaFuncSetAttribute((const void*)wo_tf32<2>,  cudaFuncAttributeMaxDynamicSharedMemorySize, SMW2);
    cudaFuncSetAttribute((const void*)attn_kernel, cudaFuncAttributeMaxDynamicSharedMemorySize, SMA);

    rot_kernel<<<EE/256, 256>>>(ev, er, rotp);

    qkv_tf32<0><<<dim3(32, 4), 256, SMF0>>>(x, Wq,         Wk,         Wv,         qp, kp, vp);
    qkv_tf32<1><<<dim3(96, 4), 256, SMF1>>>(x, Wq + 16384, Wk + 16384, Wv + 16384, qp, kp, vp);
    qkv_tf32<2><<<dim3(80, 4), 256, SMF2>>>(x, Wq + 32768, Wk + 32768, Wv + 32768, qp, kp, vp);

    attn_kernel<<<dim3(8, 128), 128, SMA>>>(qp, kp, vp, op);

    // W_o: ntiles = 128 / 384 / 640 -> grids 128 / 384 / 320 (l=2 does 2 tiles/CTA)
    wo_tf32<0><<<128, 256, SMW0>>>(op, Wo, kp);
    wo_tf32<1><<<384, 256, SMW1>>>(op, Wo, kp);
    wo_tf32<2><<<320, 256, SMW2>>>(op, Wo, kp);

    epilogue_kernel<<<NN, 256>>>(x, kp, gamma, beta, out);
}

// round 10
// speedup vs baseline: 1.4088x; 1.0095x over previous
#include <cuda_runtime.h>
#include <math.h>

#define NN 8192
#define DD 1152
#define EE 262144

typedef unsigned int uint32;

// -------- scratch (allocation-free: static device globals) --------
__device__ float g_q[(size_t)NN * DD];
__device__ float g_k[(size_t)NN * DD];
__device__ float g_v[(size_t)NN * DD];
__device__ float g_o[(size_t)NN * DD];

// -------- tf32 mma helper (HW reads regs as tf32; low bits ignored) --------
__device__ __forceinline__ void mma_tf32(float* d,
                                         uint32 a0, uint32 a1, uint32 a2, uint32 a3,
                                         uint32 b0, uint32 b1) {
    asm("mma.sync.aligned.m16n8k8.row.col.f32.tf32.tf32.f32 "
        "{%0,%1,%2,%3}, {%4,%5,%6,%7}, {%8,%9}, {%0,%1,%2,%3};"
        : "+f"(d[0]), "+f"(d[1]), "+f"(d[2]), "+f"(d[3])
        : "r"(a0), "r"(a1), "r"(a2), "r"(a3), "r"(b0), "r"(b1));
}

// -------- cp.async helpers --------
__device__ __forceinline__ void cp16(void* smem, const void* gmem) {
    uint32 s = (uint32)__cvta_generic_to_shared(smem);
    asm volatile("cp.async.cg.shared.global [%0], [%1], 16;" :: "r"(s), "l"(gmem));
}
__device__ __forceinline__ void cp_commit() { asm volatile("cp.async.commit_group;"); }
__device__ __forceinline__ void cp_wait0()  { asm volatile("cp.async.wait_group 0;"); }

// ====================== rot kernel ======================
__global__ void rot_kernel(const float* __restrict__ ev,
                           const float* __restrict__ er,
                           float* __restrict__ rot)
{
    int e = blockIdx.x * 256 + threadIdx.x;
    if (e >= EE) return;
    float vx = ev[3*e+0], vy = ev[3*e+1], vz = ev[3*e+2];
    float dist = sqrtf(vx*vx + vy*vy + vz*vz);
    float nx0 = vx/dist, nx1 = vy/dist, nx2 = vz/dist;

    float r0 = er[3*e+0]-0.5f, r1 = er[3*e+1]-0.5f, r2 = er[3*e+2]-0.5f;
    float rn = sqrtf(r0*r0 + r1*r1 + r2*r2);
    float a0 = r0/rn, a1 = r1/rn, a2 = r2/rn;
    float b0 = -a1, b1 = a0, b2 = a2;
    float c0 = a0, c1 = -a2, c2 = a1;

    float da = fabsf(a0*nx0 + a1*nx1 + a2*nx2);
    float db = fabsf(b0*nx0 + b1*nx1 + b2*nx2);
    float dc = fabsf(c0*nx0 + c1*nx1 + c2*nx2);

    float e0 = a0, e1 = a1, e2c_ = a2, dcur = da;
    if (dcur > db) { e0 = b0; e1 = b1; e2c_ = b2; dcur = db; }
    if (dcur > dc) { e0 = c0; e1 = c1; e2c_ = c2; }

    float z0 = nx1*e2c_ - nx2*e1;
    float z1 = nx2*e0   - nx0*e2c_;
    float z2 = nx0*e1   - nx1*e0;
    float zn = sqrtf(z0*z0 + z1*z1 + z2*z2);
    z0 /= zn; z1 /= zn; z2 /= zn;
    float y0 = nx1*z2 - nx2*z1;
    float y1 = nx2*z0 - nx0*z2;
    float y2 = nx0*z1 - nx1*z0;
    float yn = sqrtf(y0*y0 + y1*y1 + y2*y2);
    y0 /= yn; y1 /= yn; y2 /= yn;

    float* R = rot + (size_t)e * 9;
    R[0] =  z0; R[1] =  z1; R[2] =  z2;
    R[3] = nx0; R[4] = nx1; R[5] = nx2;
    R[6] = -y0; R[7] = -y1; R[8] = -y2;
}

#define PL 132

// ====================== fused QKV linear (reg-prefetch pipelined X) ======================
template<int L>
__global__ void __launch_bounds__(256) qkv_tf32(const float* __restrict__ x,
                                                const float* __restrict__ Wq,
                                                const float* __restrict__ Wk,
                                                const float* __restrict__ Wv,
                                                float* __restrict__ q,
                                                float* __restrict__ k,
                                                float* __restrict__ v)
{
    constexpr int d = 2*L + 1;
    constexpr int s = (L == 0) ? 0 : (L == 1 ? 128 : 512);
    constexpr int ntiles = (NN * d) / 64;
    constexpr int PX = 128*d + 4;
    constexpr int NMAX = 64/d + 2;
    constexpr int TC = NMAX*32*d;          // 16B chunks per tile
    constexpr int CH = (TC + 255)/256;     // chunks per thread (=9 for all L)

    extern __shared__ float sm[];
    float* Xs = sm;                 // [NMAX][PX] natural node rows
    float* Bs = sm + NMAX*PX;       // [3][32][132]

    const int tid  = threadIdx.x;
    const int lane = tid & 31, wid = tid >> 5;
    const int gr   = lane >> 2, th = lane & 3;
    const int wr   = wid >> 1, wc = wid & 1;
    const int obase = blockIdx.y * 32;

    for (int i = tid; i < 3*32*32; i += 256) {
        int wi = i >> 10, rem = i & 1023;
        int o = rem >> 5, c4 = (rem & 31) * 4;
        const float* wp = (wi == 0) ? Wq : (wi == 1 ? Wk : Wv);
        cp16(&Bs[(wi*32 + o)*PL + c4], &wp[(obase + o)*128 + c4]);
    }
    cp_commit();

    const float scale = 0.08838834764831845f;  // 1/sqrt(128)

    // prologue: prefetch first tile into registers
    float4 xr[CH];
    {
        const int n0 = (blockIdx.x * 64) / d;
        #pragma unroll
        for (int u = 0; u < CH; u++) {
            int i = tid + u*256;
            if (i < TC) {
                int node = i / (32*d);
                int j = (i - node*32*d) * 4;
                int nn = n0 + node; if (nn > NN-1) nn = NN-1;
                xr[u] = *(const float4*)&x[(size_t)nn*DD + s + j];
            }
        }
    }
    cp_wait0();   // W groups complete (barrier below publishes)

    for (int t = blockIdx.x; t < ntiles; t += gridDim.x) {
        const int r0 = t * 64;
        const int n0 = r0 / d;

        __syncthreads();   // previous tile's Xs readers done
        #pragma unroll
        for (int u = 0; u < CH; u++) {
            int i = tid + u*256;
            if (i < TC) {
                int node = i / (32*d);
                int j = (i - node*32*d) * 4;
                *(float4*)&Xs[node*PX + j] = xr[u];
            }
        }
        __syncthreads();   // Xs (and W on first iter) visible

        // prefetch next tile (latency hidden by mainloop)
        const int t2 = t + gridDim.x;
        if (t2 < ntiles) {
            const int n02 = (t2 * 64) / d;
            #pragma unroll
            for (int u = 0; u < CH; u++) {
                int i = tid + u*256;
                if (i < TC) {
                    int node = i / (32*d);
                    int j = (i - node*32*d) * 4;
                    int nn = n02 + node; if (nn > NN-1) nn = NN-1;
                    xr[u] = *(const float4*)&x[(size_t)nn*DD + s + j];
                }
            }
        }

        const int rowA0 = r0 + wr*16 + gr;
        const int rowA1 = rowA0 + 8;
        const int nA0 = rowA0 / d, mA0 = rowA0 - nA0*d;
        const int nA1 = rowA1 / d, mA1 = rowA1 - nA1*d;
        const float* X0 = Xs + (nA0 - n0)*PX + mA0 + th*d;
        const float* X1 = Xs + (nA1 - n0)*PX + mA1 + th*d;

        float acc[3][2][4];
        #pragma unroll
        for (int wi = 0; wi < 3; wi++)
            #pragma unroll
            for (int nt = 0; nt < 2; nt++)
                #pragma unroll
                for (int j = 0; j < 4; j++) acc[wi][nt][j] = 0.f;

        #pragma unroll 4
        for (int ks = 0; ks < 16; ks++) {
            const int co = ks * 8 * d;
            uint32 a0 = __float_as_uint(X0[co      ]);
            uint32 a1 = __float_as_uint(X1[co      ]);
            uint32 a2 = __float_as_uint(X0[co + 4*d]);
            uint32 a3 = __float_as_uint(X1[co + 4*d]);
            #pragma unroll
            for (int wi = 0; wi < 3; wi++)
                #pragma unroll
                for (int nt = 0; nt < 2; nt++) {
                    const float* Br = Bs + (wi*32 + wc*16 + nt*8 + gr)*PL + ks*8 + th;
                    uint32 b0 = __float_as_uint(Br[0]);
                    uint32 b1 = __float_as_uint(Br[4]);
                    mma_tf32(acc[wi][nt], a0, a1, a2, a3, b0, b1);
                }
        }

        #pragma unroll
        for (int wi = 0; wi < 3; wi++) {
            float* yp = (wi == 0) ? q : (wi == 1 ? k : v);
            #pragma unroll
            for (int r = 0; r < 2; r++) {
                int rg = r0 + wr*16 + gr + 8*r;
                int n = rg / d, m = rg - n * d;
                float* yb = yp + (size_t)n*DD + s + m;
                #pragma unroll
                for (int nt = 0; nt < 2; nt++) {
                    int o = obase + wc*16 + nt*8 + 2*th;
                    yb[(o  )*d] = acc[wi][nt][2*r  ] * scale;
                    yb[(o+1)*d] = acc[wi][nt][2*r+1] * scale;
                }
            }
        }
    }
}

// ====================== W_o linear (reg-prefetch pipelined X) ======================
template<int L>
__global__ void __launch_bounds__(256) wo_tf32(const float* __restrict__ x,
                                               const float* __restrict__ W,
                                               float* __restrict__ y)
{
    constexpr int d = 2*L + 1;
    constexpr int s = (L == 0) ? 0 : (L == 1 ? 128 : 512);
    constexpr int ntiles = (NN * d) / 64;
    constexpr int PX = 128*d + 4;
    constexpr int NMAX = 64/d + 2;
    constexpr int TC = NMAX*32*d;
    constexpr int CH = (TC + 255)/256;

    extern __shared__ float sm[];
    float* Xs = sm;                 // [NMAX][PX]
    float* Bs = sm + NMAX*PX;       // [128][132]

    const int tid  = threadIdx.x;
    const int lane = tid & 31, wid = tid >> 5;
    const int gr   = lane >> 2, th = lane & 3;
    const int wr   = wid >> 1, wc = wid & 1;
    const int warpRow = wr * 16;
    const int colBase = wc * 64;

    const float* Wl = W + L * 16384;
    for (int i = tid; i < 4096; i += 256) {
        int o = i >> 5, c4 = (i & 31) * 4;
        cp16(&Bs[o*PL + c4], &Wl[o*128 + c4]);
    }
    cp_commit();

    const float scale = 0.08838834764831845f;

    float4 xr[CH];
    {
        const int n0 = (blockIdx.x * 64) / d;
        #pragma unroll
        for (int u = 0; u < CH; u++) {
            int i = tid + u*256;
            if (i < TC) {
                int node = i / (32*d);
                int j = (i - node*32*d) * 4;
                int nn = n0 + node; if (nn > NN-1) nn = NN-1;
                xr[u] = *(const float4*)&x[(size_t)nn*DD + s + j];
            }
        }
    }
    cp_wait0();

    for (int t = blockIdx.x; t < ntiles; t += gridDim.x) {
        const int r0 = t * 64;
        const int n0 = r0 / d;

        __syncthreads();
        #pragma unroll
        for (int u = 0; u < CH; u++) {
            int i = tid + u*256;
            if (i < TC) {
                int node = i / (32*d);
                int j = (i - node*32*d) * 4;
                *(float4*)&Xs[node*PX + j] = xr[u];
            }
        }
        __syncthreads();

        const int t2 = t + gridDim.x;
        if (t2 < ntiles) {
            const int n02 = (t2 * 64) / d;
            #pragma unroll
            for (int u = 0; u < CH; u++) {
                int i = tid + u*256;
                if (i < TC) {
                    int node = i / (32*d);
                    int j = (i - node*32*d) * 4;
                    int nn = n02 + node; if (nn > NN-1) nn = NN-1;
                    xr[u] = *(const float4*)&x[(size_t)nn*DD + s + j];
                }
            }
        }

        const int rowA0 = r0 + warpRow + gr;
        const int rowA1 = rowA0 + 8;
        const int nA0 = rowA0 / d, mA0 = rowA0 - nA0*d;
        const int nA1 = rowA1 / d, mA1 = rowA1 - nA1*d;
        const float* X0 = Xs + (nA0 - n0)*PX + mA0 + th*d;
        const float* X1 = Xs + (nA1 - n0)*PX + mA1 + th*d;

        float acc[8][4];
        #pragma unroll
        for (int nt = 0; nt < 8; nt++)
            #pragma unroll
            for (int j = 0; j < 4; j++) acc[nt][j] = 0.f;

        #pragma unroll 4
        for (int ks = 0; ks < 16; ks++) {
            const int co = ks * 8 * d;
            uint32 a0 = __float_as_uint(X0[co      ]);
            uint32 a1 = __float_as_uint(X1[co      ]);
            uint32 a2 = __float_as_uint(X0[co + 4*d]);
            uint32 a3 = __float_as_uint(X1[co + 4*d]);
            #pragma unroll
            for (int nt = 0; nt < 8; nt++) {
                const float* Br = Bs + (colBase + nt*8 + gr) * PL + ks*8 + th;
                uint32 b0 = __float_as_uint(Br[0]);
                uint32 b1 = __float_as_uint(Br[4]);
                mma_tf32(acc[nt], a0, a1, a2, a3, b0, b1);
            }
        }

        #pragma unroll
        for (int r = 0; r < 2; r++) {
            int rg = r0 + warpRow + gr + 8*r;
            int n = rg / d, m = rg - n * d;
            float* yb = y + (size_t)n*DD + s + m;
            #pragma unroll
            for (int nt = 0; nt < 8; nt++) {
                int o = colBase + nt*8 + 2*th;
                yb[(o  )*d] = acc[nt][2*r  ] * scale;
                yb[(o+1)*d] = acc[nt][2*r+1] * scale;
            }
        }
    }
}

// ====================== flash attention (TF32, cp.async fills; R6/R8-proven) ======================
#define PQ 148
#define PVP 152
#define PP 52

__global__ void __launch_bounds__(128) attn_kernel(const float* __restrict__ q,
                                                   const float* __restrict__ k,
                                                   const float* __restrict__ v,
                                                   float* __restrict__ o)
{
    extern __shared__ float sm[];
    float* Qs = sm;               // [64][148]
    float* Ks = Qs + 64*PQ;       // [32][148]
    float* Vs = Ks + 32*PQ;       // [32][152]
    float* Ps = Vs + 32*PVP;      // [64][52]

    const int tid  = threadIdx.x;
    const int wid  = tid >> 5, lane = tid & 31;
    const int gr   = lane >> 2, th = lane & 3;
    const int b    = blockIdx.y >> 3, h = blockIdx.y & 7;
    const int q0   = blockIdx.x * 64;
    const size_t hoff  = (size_t)h * 144;
    const size_t bbase = (size_t)b * 512;
    const float qscale = 1.0f / 12.0f;

    for (int f = tid; f < 64*36; f += 128) {
        int row = f / 36, cs = (f % 36) * 4;
        cp16(&Qs[row*PQ + cs], &q[(bbase + q0 + row) * DD + hoff + cs]);
    }
    cp_commit();

    float m_i[2] = {-1e30f, -1e30f};
    float l_i[2] = {0.f, 0.f};
    float oac[18][4];
    #pragma unroll
    for (int nt = 0; nt < 18; nt++)
        #pragma unroll
        for (int j = 0; j < 4; j++) oac[nt][j] = 0.f;

    const int warpRow = 16 * wid;

    for (int kt = 0; kt < 512; kt += 32) {
        __syncthreads();
        for (int f = tid; f < 32*36; f += 128) {
            int row = f / 36, cs = (f % 36) * 4;
            size_t g = (bbase + kt + row) * (size_t)DD + hoff + cs;
            cp16(&Ks[row*PQ  + cs], &k[g]);
            cp16(&Vs[row*PVP + cs], &v[g]);
        }
        cp_commit();
        cp_wait0();
        __syncthreads();

        float s_[4][4];
        #pragma unroll
        for (int nt = 0; nt < 4; nt++)
            #pragma unroll
            for (int j = 0; j < 4; j++) s_[nt][j] = 0.f;

        #pragma unroll 3
        for (int ks = 0; ks < 18; ks++) {
            int k0 = ks * 8;
            const float* Qr = Qs + k0 + th;
            uint32 a0 = __float_as_uint(Qr[(warpRow + gr    ) * PQ    ]);
            uint32 a1 = __float_as_uint(Qr[(warpRow + gr + 8) * PQ    ]);
            uint32 a2 = __float_as_uint(Qr[(warpRow + gr    ) * PQ + 4]);
            uint32 a3 = __float_as_uint(Qr[(warpRow + gr + 8) * PQ + 4]);
            #pragma unroll
            for (int nt = 0; nt < 4; nt++) {
                const float* Kr = Ks + (nt*8 + gr) * PQ + k0 + th;
                uint32 b0 = __float_as_uint(Kr[0]);
                uint32 b1 = __float_as_uint(Kr[4]);
                mma_tf32(s_[nt], a0, a1, a2, a3, b0, b1);
            }
        }

        #pragma unroll
        for (int nt = 0; nt < 4; nt++)
            #pragma unroll
            for (int j = 0; j < 4; j++) s_[nt][j] *= qscale;

        #pragma unroll
        for (int r = 0; r < 2; r++) {
            float rm = -1e30f;
            #pragma unroll
            for (int nt = 0; nt < 4; nt++)
                rm = fmaxf(rm, fmaxf(s_[nt][2*r], s_[nt][2*r+1]));
            rm = fmaxf(rm, __shfl_xor_sync(0xffffffffu, rm, 1));
            rm = fmaxf(rm, __shfl_xor_sync(0xffffffffu, rm, 2));
            float newm = fmaxf(m_i[r], rm);
            float rs = 0.f;
            #pragma unroll
            for (int nt = 0; nt < 4; nt++) {
                float p0 = __expf(s_[nt][2*r  ] - newm);
                float p1 = __expf(s_[nt][2*r+1] - newm);
                s_[nt][2*r] = p0; s_[nt][2*r+1] = p1;
                rs += p0 + p1;
            }
            rs += __shfl_xor_sync(0xffffffffu, rs, 1);
            rs += __shfl_xor_sync(0xffffffffu, rs, 2);
            float corr = __expf(m_i[r] - newm);
            l_i[r] = l_i[r] * corr + rs;
            m_i[r] = newm;
            #pragma unroll
            for (int nt = 0; nt < 18; nt++) {
                oac[nt][2*r  ] *= corr;
                oac[nt][2*r+1] *= corr;
            }
        }

        #pragma unroll
        for (int nt = 0; nt < 4; nt++) {
            int col = nt*8 + 2*th;
            Ps[(warpRow + gr    ) * PP + col    ] = s_[nt][0];
            Ps[(warpRow + gr    ) * PP + col + 1] = s_[nt][1];
            Ps[(warpRow + gr + 8) * PP + col    ] = s_[nt][2];
            Ps[(warpRow + gr + 8) * PP + col + 1] = s_[nt][3];
        }
        __syncwarp();

        #pragma unroll
        for (int ks = 0; ks < 4; ks++) {
            int k0 = ks * 8;
            const float* Pr = Ps + k0 + th;
            uint32 a0 = __float_as_uint(Pr[(warpRow + gr    ) * PP    ]);
            uint32 a1 = __float_as_uint(Pr[(warpRow + gr + 8) * PP    ]);
            uint32 a2 = __float_as_uint(Pr[(warpRow + gr    ) * PP + 4]);
            uint32 a3 = __float_as_uint(Pr[(warpRow + gr + 8) * PP + 4]);
            const float* Vb = Vs + (k0 + th) * PVP + gr;
            #pragma unroll
            for (int nt = 0; nt < 18; nt++) {
                uint32 b0 = __float_as_uint(Vb[nt*8]);
                uint32 b1 = __float_as_uint(Vb[nt*8 + 4*PVP]);
                mma_tf32(oac[nt], a0, a1, a2, a3, b0, b1);
            }
        }
    }

    #pragma unroll
    for (int r = 0; r < 2; r++) {
        float inv = 1.0f / l_i[r];
        int row = q0 + warpRow + gr + 8*r;
        float* ob = o + (bbase + row) * (size_t)DD + hoff;
        #pragma unroll
        for (int nt = 0; nt < 18; nt++) {
            int col = nt*8 + 2*th;
            ob[col    ] = oac[nt][2*r  ] * inv;
            ob[col + 1] = oac[nt][2*r+1] * inv;
        }
    }
}

// ====================== epilogue ======================
__global__ void __launch_bounds__(256) epilogue_kernel(const float* __restrict__ x,
                                                       const float* __restrict__ attn,
                                                       const float* __restrict__ gamma,
                                                       const float* __restrict__ beta,
                                                       float* __restrict__ out)
{
    const int n = blockIdx.x;
    const int tid = threadIdx.x;
    const size_t base = (size_t)n * DD;

    __shared__ float red[8];
    __shared__ float mu_s, rv_s;

    float val = 0.f;
    if (tid < 128) val = x[base + tid] + attn[base + tid];
    float s1 = val, s2 = val * val;
    #pragma unroll
    for (int off = 16; off; off >>= 1) {
        s1 += __shfl_xor_sync(0xffffffffu, s1, off);
        s2 += __shfl_xor_sync(0xffffffffu, s2, off);
    }
    if (tid < 128 && (tid & 31) == 0) { red[(tid>>5)*2] = s1; red[(tid>>5)*2+1] = s2; }
    __syncthreads();
    if (tid == 0) {
        float t1 = red[0] + red[2] + red[4] + red[6];
        float t2 = red[1] + red[3] + red[5] + red[7];
        float mu = t1 * (1.f/128.f);
        float var = t2 * (1.f/128.f) - mu*mu;
        mu_s = mu;
        rv_s = rsqrtf(var + 1e-5f);
    }
    __syncthreads();
    const float mu = mu_s, rv = rv_s;

    for (int i = tid; i < DD; i += 256) {
        float vv = x[base + i] + attn[base + i];
        if (i < 128) {
            float z = (vv - mu) * rv * gamma[i] + beta[i];
            vv = z / (1.f + __expf(-z));
        }
        out[base + i] = vv;
    }
}

// ====================== launch ======================
extern "C" void kernel_launch(void* const* d_in, const int* in_sizes, int n_in,
                              void* d_out, int out_size)
{
    const float* x     = (const float*)d_in[0];
    const float* ev    = (const float*)d_in[1];
    const float* er    = (const float*)d_in[2];
    const float* Wq    = (const float*)d_in[3];
    const float* Wk    = (const float*)d_in[4];
    const float* Wv    = (const float*)d_in[5];
    const float* Wo    = (const float*)d_in[6];
    const float* gamma = (const float*)d_in[7];
    const float* beta  = (const float*)d_in[8];
    float* out  = (float*)d_out;
    float* rotp = out + (size_t)NN * DD;

    float *qp, *kp, *vp, *op;
    cudaGetSymbolAddress((void**)&qp, g_q);
    cudaGetSymbolAddress((void**)&kp, g_k);
    cudaGetSymbolAddress((void**)&vp, g_v);
    cudaGetSymbolAddress((void**)&op, g_o);

    const int SMF0 = (66*132 + 96*PL) * 4;   // 85536
    const int SMF1 = (23*388 + 96*PL) * 4;   // 86384
    const int SMF2 = (14*644 + 96*PL) * 4;   // 86752
    const int SMW0 = (66*132 + 128*PL) * 4;  // 102432
    const int SMW1 = (23*388 + 128*PL) * 4;  // 103280
    const int SMW2 = (14*644 + 128*PL) * 4;  // 103648
    const int SMA  = (64*PQ + 32*PQ + 32*PVP + 64*PP) * 4;  // 89600

    cudaFuncSetAttribute((const void*)qkv_tf32<0>, cudaFuncAttributeMaxDynamicSharedMemorySize, SMF0);
    cudaFuncSetAttribute((const void*)qkv_tf32<1>, cudaFuncAttributeMaxDynamicSharedMemorySize, SMF1);
    cudaFuncSetAttribute((const void*)qkv_tf32<2>, cudaFuncAttributeMaxDynamicSharedMemorySize, SMF2);
    cudaFuncSetAttribute((const void*)wo_tf32<0>,  cudaFuncAttributeMaxDynamicSharedMemorySize, SMW0);
    cudaFuncSetAttribute((const void*)wo_tf32<1>,  cudaFuncAttributeMaxDynamicSharedMemorySize, SMW1);
    cudaFuncSetAttribute((const void*)wo_tf32<2>,  cudaFuncAttributeMaxDynamicSharedMemorySize, SMW2);
    cudaFuncSetAttribute((const void*)attn_kernel, cudaFuncAttributeMaxDynamicSharedMemorySize, SMA);

    rot_kernel<<<EE/256, 256>>>(ev, er, rotp);

    qkv_tf32<0><<<dim3(32, 4), 256, SMF0>>>(x, Wq,         Wk,         Wv,         qp, kp, vp);
    qkv_tf32<1><<<dim3(96, 4), 256, SMF1>>>(x, Wq + 16384, Wk + 16384, Wv + 16384, qp, kp, vp);
    qkv_tf32<2><<<dim3(80, 4), 256, SMF2>>>(x, Wq + 32768, Wk + 32768, Wv + 32768, qp, kp, vp);

    attn_kernel<<<dim3(8, 128), 128, SMA>>>(qp, kp, vp, op);

    wo_tf32<0><<<128, 256, SMW0>>>(op, Wo, kp);
    wo_tf32<1><<<384, 256, SMW1>>>(op, Wo, kp);
    wo_tf32<2><<<320, 256, SMW2>>>(op, Wo, kp);

    epilogue_kernel<<<NN, 256>>>(x, kp, gamma, beta, out);
}